// round 12
// baseline (speedup 1.0000x reference)
#include <cuda_runtime.h>
#include <cuda_bf16.h>
#include <cstdint>

#define NN   50000
#define EE   800000
#define FIN  32
#define HH   128
#define LN_EPS 1e-5f
#define NB   ((NN + 255) / 256)   // 196 scan blocks
#define NTILES ((NN + 127) / 128) // 391 GEMM tiles

// ---------------- scratch (static device allocations only) ----------------
__device__ float g_h0[NN * HH];
__device__ float g_h1[NN * HH];
__device__ __nv_bfloat16 g_h0b[NN * HH];  // bf16 shadow of h0 (gather feed)
__device__ __nv_bfloat16 g_h1b[NN * HH];  // bf16 shadow of h1 (gather feed)
__device__ float g_agg[NN * HH];
__device__ float g_inv[NN];
__device__ int   g_cnt[NN];
__device__ int   g_off[NN];
__device__ int   g_pos[NN];
__device__ int   g_adj[EE];
__device__ int   g_bsum[NB];
__device__ int   g_bpre[NB];

// ---------------- mma.sync tf32 helpers ----------------
__device__ __forceinline__ uint32_t f2tf32(float x) {
    uint32_t r;
    asm("cvt.rna.tf32.f32 %0, %1;" : "=r"(r) : "f"(x));
    return r;
}

__device__ __forceinline__ void mma_tf32(float* acc, uint32_t a0, uint32_t a1,
                                         uint32_t a2, uint32_t a3,
                                         uint32_t b0, uint32_t b1) {
    asm volatile(
        "mma.sync.aligned.m16n8k8.row.col.f32.tf32.tf32.f32 "
        "{%0,%1,%2,%3}, {%4,%5,%6,%7}, {%8,%9}, {%0,%1,%2,%3};"
        : "+f"(acc[0]), "+f"(acc[1]), "+f"(acc[2]), "+f"(acc[3])
        : "r"(a0), "r"(a1), "r"(a2), "r"(a3), "r"(b0), "r"(b1));
}

// ---------------- zero degree counters ----------------
__global__ void zero_cnt_kernel() {
    int i = blockIdx.x * blockDim.x + threadIdx.x;
    if (i < NN) g_cnt[i] = 0;
}

// ---------------- input projection ----------------
__global__ void input_proj_kernel(const float* __restrict__ x,
                                  const float* __restrict__ w,
                                  const float* __restrict__ b) {
    __shared__ float sw[FIN * HH];
    __shared__ float sb[HH];
    int tid = threadIdx.x;
    for (int i = tid; i < FIN * HH; i += 256) sw[i] = w[i];
    if (tid < HH) sb[tid] = b[tid];
    __syncthreads();

    int j = tid & 127;
    int half = tid >> 7;
    for (int n = blockIdx.x * 2 + half; n < NN; n += gridDim.x * 2) {
        const float4* xr = reinterpret_cast<const float4*>(x + n * FIN);
        float acc = sb[j];
#pragma unroll
        for (int k4 = 0; k4 < FIN / 4; k4++) {
            float4 xv = xr[k4];
            int k = k4 * 4;
            acc = fmaf(xv.x, sw[(k + 0) * HH + j], acc);
            acc = fmaf(xv.y, sw[(k + 1) * HH + j], acc);
            acc = fmaf(xv.z, sw[(k + 2) * HH + j], acc);
            acc = fmaf(xv.w, sw[(k + 3) * HH + j], acc);
        }
        float r = fmaxf(acc, 0.f);
        g_h0[n * HH + j] = r;
        g_h0b[n * HH + j] = __float2bfloat16(r);
    }
}

// ---------------- degree count ----------------
__global__ void count_kernel(const int* __restrict__ tgt) {
    int i = blockIdx.x * blockDim.x + threadIdx.x;
    if (i < EE) atomicAdd(&g_cnt[tgt[i]], 1);
}

// ---------------- parallel scan ----------------
__global__ void scan1_kernel() {
    int blk = blockIdx.x;
    int t = threadIdx.x;
    int i = blk * 256 + t;
    int c = (i < NN) ? g_cnt[i] : 0;

    int lane = t & 31, w = t >> 5;
    int v = c;
#pragma unroll
    for (int o = 1; o < 32; o <<= 1) {
        int u = __shfl_up_sync(0xffffffffu, v, o);
        if (lane >= o) v += u;
    }
    __shared__ int wsum[8];
    if (lane == 31) wsum[w] = v;
    __syncthreads();
    if (w == 0 && lane < 8) {
        int s = wsum[lane];
#pragma unroll
        for (int o = 1; o < 8; o <<= 1) {
            int u = __shfl_up_sync(0xffu, s, o);
            if (lane >= o) s += u;
        }
        wsum[lane] = s;
    }
    __syncthreads();
    int incl = v + ((w > 0) ? wsum[w - 1] : 0);
    if (i < NN) g_off[i] = incl - c;
    if (t == 255) g_bsum[blk] = incl;
}

__global__ void scan2_kernel() {
    int t = threadIdx.x;
    int c = (t < NB) ? g_bsum[t] : 0;
    int lane = t & 31, w = t >> 5;
    int v = c;
#pragma unroll
    for (int o = 1; o < 32; o <<= 1) {
        int u = __shfl_up_sync(0xffffffffu, v, o);
        if (lane >= o) v += u;
    }
    __shared__ int wsum[8];
    if (lane == 31) wsum[w] = v;
    __syncthreads();
    if (w == 0 && lane < 8) {
        int s = wsum[lane];
#pragma unroll
        for (int o = 1; o < 8; o <<= 1) {
            int u = __shfl_up_sync(0xffu, s, o);
            if (lane >= o) s += u;
        }
        wsum[lane] = s;
    }
    __syncthreads();
    int incl = v + ((w > 0) ? wsum[w - 1] : 0);
    if (t < NB) g_bpre[t] = incl - c;
}

__global__ void scan3_kernel() {
    int i = blockIdx.x * blockDim.x + threadIdx.x;
    if (i < NN) {
        int o = g_off[i] + g_bpre[i >> 8];
        g_off[i] = o;
        g_pos[i] = o;
        g_inv[i] = 1.0f / fmaxf((float)g_cnt[i], 1.0f);
    }
}

// ---------------- CSR fill ----------------
__global__ void fill_kernel(const int* __restrict__ src,
                            const int* __restrict__ tgt) {
    int e = blockIdx.x * blockDim.x + threadIdx.x;
    if (e < EE) {
        int p = atomicAdd(&g_pos[tgt[e]], 1);
        g_adj[p] = src[e];
    }
}

// ---------------- gather (bf16 rows, fp32 accumulate) ----------------
template <int WHICH>
__global__ void gather_kernel() {
    const __nv_bfloat16* __restrict__ h = (WHICH == 0) ? g_h0b : g_h1b;
    int idx = blockIdx.x * blockDim.x + threadIdx.x;
    int node = idx >> 5;
    if (node >= NN) return;
    int lane = idx & 31;
    int fb = lane * 4;                      // 4 features per lane

    int beg = g_off[node];
    int cnt = g_cnt[node];
    float4 acc = make_float4(0.f, 0.f, 0.f, 0.f);

    int i = 0;
    for (; i + 4 <= cnt; i += 4) {
        int s0 = __ldg(&g_adj[beg + i + 0]);
        int s1 = __ldg(&g_adj[beg + i + 1]);
        int s2 = __ldg(&g_adj[beg + i + 2]);
        int s3 = __ldg(&g_adj[beg + i + 3]);
        uint2 r0 = *reinterpret_cast<const uint2*>(h + s0 * HH + fb);
        uint2 r1 = *reinterpret_cast<const uint2*>(h + s1 * HH + fb);
        uint2 r2 = *reinterpret_cast<const uint2*>(h + s2 * HH + fb);
        uint2 r3 = *reinterpret_cast<const uint2*>(h + s3 * HH + fb);
#pragma unroll
        for (int u = 0; u < 4; u++) {
            uint2 r = (u == 0) ? r0 : (u == 1) ? r1 : (u == 2) ? r2 : r3;
            float2 lo = __bfloat1622float2(
                *reinterpret_cast<const __nv_bfloat162*>(&r.x));
            float2 hi = __bfloat1622float2(
                *reinterpret_cast<const __nv_bfloat162*>(&r.y));
            acc.x += lo.x; acc.y += lo.y; acc.z += hi.x; acc.w += hi.y;
        }
    }
    for (; i < cnt; i++) {
        int s = __ldg(&g_adj[beg + i]);
        uint2 r = *reinterpret_cast<const uint2*>(h + s * HH + fb);
        float2 lo = __bfloat1622float2(
            *reinterpret_cast<const __nv_bfloat162*>(&r.x));
        float2 hi = __bfloat1622float2(
            *reinterpret_cast<const __nv_bfloat162*>(&r.y));
        acc.x += lo.x; acc.y += lo.y; acc.z += hi.x; acc.w += hi.y;
    }
    float iv = g_inv[node];
    acc.x *= iv; acc.y *= iv; acc.z *= iv; acc.w *= iv;
    *reinterpret_cast<float4*>(g_agg + node * HH + fb) = acc;
}

// ================= fused GCN layer via mma.sync tf32 =================
// 512 threads = 16 warps: warp grid 8 (m) x 2 (n); warp tile 16 x 64.
// CTA tile: 128 nodes x 128 cols; K = 128 per matrix, 2 matrices (h@ws + agg@wn).
#define SM_B2_F   0
#define SM_A_F    32768
#define SM_RS_F   49664
#define SM_RQ_F   49920
#define SM_G_F    50176
#define SM_BE_F   50304
#define SM_BI_F   50432
#define GCN_SMEM  (50560 * 4)
#define APITCH    132

template <int LAYER>
__global__ void __launch_bounds__(512, 1)
gcn_kernel(const float* __restrict__ ws, const float* __restrict__ bs,
           const float* __restrict__ wn, const float* __restrict__ bn,
           const float* __restrict__ gamma, const float* __restrict__ beta,
           float* __restrict__ out_param) {
    extern __shared__ float sm[];
    float2* B2   = reinterpret_cast<float2*>(sm + SM_B2_F);
    float*  sA   = sm + SM_A_F;
    float*  sredS = sm + SM_RS_F;
    float*  sredQ = sm + SM_RQ_F;
    float*  sg   = sm + SM_G_F;
    float*  sbe  = sm + SM_BE_F;
    float*  sbias = sm + SM_BI_F;

    const float* __restrict__ h_in = (LAYER == 0) ? g_h0 : g_h1;
    float* __restrict__ out = (LAYER == 0) ? g_h1 : out_param;

    int tid = threadIdx.x;
    int lane = tid & 31, wid = tid >> 5;
    int mr = wid >> 1;
    int wc = wid & 1;
    int ql = lane & 3, qr = lane >> 2;

    // ---- one-time: permute weights into B-fragment layout ----
    for (int e = tid; e < 16384; e += 512) {
        int l  = e & 31;
        int nf = (e >> 5) & 15;
        int s  = (e >> 9) & 15;
        int mat = e >> 13;
        const float* __restrict__ w = mat ? wn : ws;
        int k = s * 8 + (l & 3);
        int n = nf * 8 + (l >> 2);
        float2 b;
        b.x = __uint_as_float(f2tf32(w[k * HH + n]));
        b.y = __uint_as_float(f2tf32(w[(k + 4) * HH + n]));
        B2[e] = b;
    }
    for (int i = tid; i < HH; i += 512) {
        sg[i] = gamma[i];
        sbe[i] = beta[i];
        sbias[i] = bs[i] + bn[i];
    }
    __syncthreads();

    for (int tile = blockIdx.x; tile < NTILES; tile += gridDim.x) {
        int base = tile * 128;

        float acc[8][4];
#pragma unroll
        for (int nf = 0; nf < 8; nf++)
#pragma unroll
            for (int i = 0; i < 4; i++) acc[nf][i] = 0.f;

#pragma unroll
        for (int mat = 0; mat < 2; mat++) {
            const float* __restrict__ src = mat ? g_agg : h_in;
#pragma unroll
            for (int q = 0; q < 8; q++) {
                int id = q * 512 + tid;
                int r = id >> 5, c4 = (id & 31) * 4;
                int node = base + r;
                float4 v = make_float4(0.f, 0.f, 0.f, 0.f);
                if (node < NN)
                    v = *reinterpret_cast<const float4*>(src + node * HH + c4);
                float4 t;
                t.x = __uint_as_float(f2tf32(v.x));
                t.y = __uint_as_float(f2tf32(v.y));
                t.z = __uint_as_float(f2tf32(v.z));
                t.w = __uint_as_float(f2tf32(v.w));
                *reinterpret_cast<float4*>(sA + r * APITCH + c4) = t;
            }
            __syncthreads();

            int r0 = mr * 16 + qr;
            for (int s = 0; s < 16; s++) {
                int k = s * 8 + ql;
                uint32_t a0 = __float_as_uint(sA[r0 * APITCH + k]);
                uint32_t a1 = __float_as_uint(sA[(r0 + 8) * APITCH + k]);
                uint32_t a2 = __float_as_uint(sA[r0 * APITCH + k + 4]);
                uint32_t a3 = __float_as_uint(sA[(r0 + 8) * APITCH + k + 4]);
                const float2* bp = B2 + ((mat * 16 + s) * 16 + wc * 8) * 32 + lane;
#pragma unroll
                for (int nf = 0; nf < 8; nf++) {
                    float2 b = bp[nf * 32];
                    mma_tf32(acc[nf], a0, a1, a2, a3,
                             __float_as_uint(b.x), __float_as_uint(b.y));
                }
            }
            __syncthreads();
        }

        // ---- epilogue ----
        int row_lo = mr * 16 + qr;
        int row_hi = row_lo + 8;
        float s_lo = 0.f, q_lo = 0.f, s_hi = 0.f, q_hi = 0.f;
#pragma unroll
        for (int nf = 0; nf < 8; nf++) {
            int c0 = wc * 64 + nf * 8 + 2 * ql;
            acc[nf][0] += sbias[c0];
            acc[nf][1] += sbias[c0 + 1];
            acc[nf][2] += sbias[c0];
            acc[nf][3] += sbias[c0 + 1];
            s_lo += acc[nf][0] + acc[nf][1];
            q_lo += acc[nf][0] * acc[nf][0] + acc[nf][1] * acc[nf][1];
            s_hi += acc[nf][2] + acc[nf][3];
            q_hi += acc[nf][2] * acc[nf][2] + acc[nf][3] * acc[nf][3];
        }
#pragma unroll
        for (int o = 1; o <= 2; o <<= 1) {
            s_lo += __shfl_xor_sync(0xffffffffu, s_lo, o);
            q_lo += __shfl_xor_sync(0xffffffffu, q_lo, o);
            s_hi += __shfl_xor_sync(0xffffffffu, s_hi, o);
            q_hi += __shfl_xor_sync(0xffffffffu, q_hi, o);
        }
        if (ql == 0) {
            sredS[row_lo * 2 + wc] = s_lo;
            sredQ[row_lo * 2 + wc] = q_lo;
            sredS[row_hi * 2 + wc] = s_hi;
            sredQ[row_hi * 2 + wc] = q_hi;
        }
        __syncthreads();
        float S_lo = sredS[row_lo * 2] + sredS[row_lo * 2 + 1];
        float Q_lo = sredQ[row_lo * 2] + sredQ[row_lo * 2 + 1];
        float S_hi = sredS[row_hi * 2] + sredS[row_hi * 2 + 1];
        float Q_hi = sredQ[row_hi * 2] + sredQ[row_hi * 2 + 1];
        float mean_lo = S_lo * (1.0f / HH);
        float var_lo = Q_lo * (1.0f / HH) - mean_lo * mean_lo;
        float rstd_lo = rsqrtf(var_lo + LN_EPS);
        float mean_hi = S_hi * (1.0f / HH);
        float var_hi = Q_hi * (1.0f / HH) - mean_hi * mean_hi;
        float rstd_hi = rsqrtf(var_hi + LN_EPS);

        int node_lo = base + row_lo;
        int node_hi = base + row_hi;
#pragma unroll
        for (int nf = 0; nf < 8; nf++) {
            int c0 = wc * 64 + nf * 8 + 2 * ql;
            float g0v = sg[c0], g1v = sg[c0 + 1];
            float b0v = sbe[c0], b1v = sbe[c0 + 1];
            if (node_lo < NN) {
                float2 y;
                y.x = (acc[nf][0] - mean_lo) * rstd_lo * g0v + b0v;
                y.y = (acc[nf][1] - mean_lo) * rstd_lo * g1v + b1v;
                if (LAYER == 0) {
                    float2 res = *reinterpret_cast<const float2*>(
                        h_in + node_lo * HH + c0);
                    y.x = fmaxf(y.x, 0.f) + res.x;
                    y.y = fmaxf(y.y, 0.f) + res.y;
                    *reinterpret_cast<__nv_bfloat162*>(g_h1b + node_lo * HH + c0) =
                        __float22bfloat162_rn(make_float2(y.x, y.y));
                }
                *reinterpret_cast<float2*>(out + node_lo * HH + c0) = y;
            }
            if (node_hi < NN) {
                float2 y;
                y.x = (acc[nf][2] - mean_hi) * rstd_hi * g0v + b0v;
                y.y = (acc[nf][3] - mean_hi) * rstd_hi * g1v + b1v;
                if (LAYER == 0) {
                    float2 res = *reinterpret_cast<const float2*>(
                        h_in + node_hi * HH + c0);
                    y.x = fmaxf(y.x, 0.f) + res.x;
                    y.y = fmaxf(y.y, 0.f) + res.y;
                    *reinterpret_cast<__nv_bfloat162*>(g_h1b + node_hi * HH + c0) =
                        __float22bfloat162_rn(make_float2(y.x, y.y));
                }
                *reinterpret_cast<float2*>(out + node_hi * HH + c0) = y;
            }
        }
        __syncthreads();
    }
}

// ---------------- launch ----------------
extern "C" void kernel_launch(void* const* d_in, const int* in_sizes, int n_in,
                              void* d_out, int out_size) {
    const float* x    = (const float*)d_in[0];
    const int*   ei   = (const int*)d_in[1];
    const float* w_in = (const float*)d_in[2];
    const float* b_in = (const float*)d_in[3];
    const float* ws0  = (const float*)d_in[4];
    const float* bs0  = (const float*)d_in[5];
    const float* wn0  = (const float*)d_in[6];
    const float* bn0  = (const float*)d_in[7];
    const float* g0   = (const float*)d_in[8];
    const float* be0  = (const float*)d_in[9];
    const float* ws1  = (const float*)d_in[10];
    const float* bs1  = (const float*)d_in[11];
    const float* wn1  = (const float*)d_in[12];
    const float* bn1  = (const float*)d_in[13];
    const float* g1   = (const float*)d_in[14];
    const float* be1  = (const float*)d_in[15];
    float* out = (float*)d_out;

    const int* src = ei;
    const int* tgt = ei + EE;

    cudaFuncSetAttribute(gcn_kernel<0>, cudaFuncAttributeMaxDynamicSharedMemorySize, GCN_SMEM);
    cudaFuncSetAttribute(gcn_kernel<1>, cudaFuncAttributeMaxDynamicSharedMemorySize, GCN_SMEM);

    zero_cnt_kernel<<<(NN + 255) / 256, 256>>>();
    input_proj_kernel<<<512, 256>>>(x, w_in, b_in);
    count_kernel<<<(EE + 255) / 256, 256>>>(tgt);
    scan1_kernel<<<NB, 256>>>();
    scan2_kernel<<<1, 256>>>();
    scan3_kernel<<<NB, 256>>>();
    fill_kernel<<<(EE + 255) / 256, 256>>>(src, tgt);
    gather_kernel<0><<<(NN * 32 + 255) / 256, 256>>>();
    gcn_kernel<0><<<148, 512, GCN_SMEM>>>(ws0, bs0, wn0, bn0, g0, be0, nullptr);
    gather_kernel<1><<<(NN * 32 + 255) / 256, 256>>>();
    gcn_kernel<1><<<148, 512, GCN_SMEM>>>(ws1, bs1, wn1, bn1, g1, be1, out);
}

// round 13
// speedup vs baseline: 1.4072x; 1.4072x over previous
#include <cuda_runtime.h>
#include <cuda_bf16.h>
#include <cstdint>

#define NN   50000
#define EE   800000
#define FIN  32
#define HH   128
#define LN_EPS 1e-5f
#define NB   ((NN + 255) / 256)   // 196 scan blocks
#define NTILES ((NN + 127) / 128) // 391 GEMM tiles

// ---------------- scratch (static device allocations only) ----------------
__device__ float g_h0[NN * HH];
__device__ float g_h1[NN * HH];
__device__ float g_agg[NN * HH];
__device__ float g_inv[NN];
__device__ int   g_cnt[NN];
__device__ int   g_off[NN];
__device__ int   g_pos[NN];
__device__ int   g_adj[EE];
__device__ unsigned long long g_state[NB];  // lookback: (status<<32)|value

// ---------------- mma.sync tf32 helpers ----------------
__device__ __forceinline__ uint32_t f2tf32(float x) {
    uint32_t r;
    asm("cvt.rna.tf32.f32 %0, %1;" : "=r"(r) : "f"(x));
    return r;
}

__device__ __forceinline__ void mma_tf32(float* acc, uint32_t a0, uint32_t a1,
                                         uint32_t a2, uint32_t a3,
                                         uint32_t b0, uint32_t b1) {
    asm volatile(
        "mma.sync.aligned.m16n8k8.row.col.f32.tf32.tf32.f32 "
        "{%0,%1,%2,%3}, {%4,%5,%6,%7}, {%8,%9}, {%0,%1,%2,%3};"
        : "+f"(acc[0]), "+f"(acc[1]), "+f"(acc[2]), "+f"(acc[3])
        : "r"(a0), "r"(a1), "r"(a2), "r"(a3), "r"(b0), "r"(b1));
}

// ---------------- input projection (+ zero counters & scan state) ----------------
__global__ void input_proj_kernel(const float* __restrict__ x,
                                  const float* __restrict__ w,
                                  const float* __restrict__ b) {
    __shared__ float sw[FIN * HH];
    __shared__ float sb[HH];
    int tid = threadIdx.x;
    // zero g_cnt / g_state (grid-stride; completes before count_kernel launch)
    for (int i = blockIdx.x * blockDim.x + tid; i < NN; i += gridDim.x * blockDim.x)
        g_cnt[i] = 0;
    for (int i = blockIdx.x * blockDim.x + tid; i < NB; i += gridDim.x * blockDim.x)
        g_state[i] = 0ull;

    for (int i = tid; i < FIN * HH; i += 256) sw[i] = w[i];
    if (tid < HH) sb[tid] = b[tid];
    __syncthreads();

    int j = tid & 127;
    int half = tid >> 7;
    for (int n = blockIdx.x * 2 + half; n < NN; n += gridDim.x * 2) {
        const float4* xr = reinterpret_cast<const float4*>(x + n * FIN);
        float acc = sb[j];
#pragma unroll
        for (int k4 = 0; k4 < FIN / 4; k4++) {
            float4 xv = xr[k4];
            int k = k4 * 4;
            acc = fmaf(xv.x, sw[(k + 0) * HH + j], acc);
            acc = fmaf(xv.y, sw[(k + 1) * HH + j], acc);
            acc = fmaf(xv.z, sw[(k + 2) * HH + j], acc);
            acc = fmaf(xv.w, sw[(k + 3) * HH + j], acc);
        }
        g_h0[n * HH + j] = fmaxf(acc, 0.f);
    }
}

// ---------------- degree count ----------------
__global__ void count_kernel(const int* __restrict__ tgt) {
    int i = blockIdx.x * blockDim.x + threadIdx.x;
    if (i < EE) atomicAdd(&g_cnt[tgt[i]], 1);
}

// ---------------- single-pass decoupled-lookback scan ----------------
// status in bits[33:32]: 1 = aggregate ready, 2 = inclusive prefix ready
__global__ void scan_kernel() {
    int blk = blockIdx.x;
    int t = threadIdx.x;
    int i = blk * 256 + t;
    int c = (i < NN) ? g_cnt[i] : 0;

    int lane = t & 31, w = t >> 5;
    int v = c;
#pragma unroll
    for (int o = 1; o < 32; o <<= 1) {
        int u = __shfl_up_sync(0xffffffffu, v, o);
        if (lane >= o) v += u;
    }
    __shared__ int wsum[8];
    __shared__ int s_exc;
    if (lane == 31) wsum[w] = v;
    __syncthreads();
    if (w == 0 && lane < 8) {
        int s = wsum[lane];
#pragma unroll
        for (int o = 1; o < 8; o <<= 1) {
            int u = __shfl_up_sync(0xffu, s, o);
            if (lane >= o) s += u;
        }
        wsum[lane] = s;
    }
    __syncthreads();
    int incl = v + ((w > 0) ? wsum[w - 1] : 0);   // inclusive within block
    int agg = wsum[7];                            // block total

    // publish + lookback (thread 0)
    if (t == 0) {
        unsigned long long pub;
        if (blk == 0) {
            pub = (2ull << 32) | (unsigned long long)(unsigned)agg;
            atomicExch(&g_state[0], pub);
            s_exc = 0;
        } else {
            pub = (1ull << 32) | (unsigned long long)(unsigned)agg;
            atomicExch(&g_state[blk], pub);
            int exc = 0;
            int p = blk - 1;
            while (p >= 0) {
                unsigned long long st = atomicAdd(&g_state[p], 0ull);  // volatile read
                unsigned status = (unsigned)(st >> 32);
                if (status == 0u) continue;          // not ready, spin
                int val = (int)(unsigned)st;
                exc += val;
                if (status == 2u) break;             // inclusive prefix: done
                p--;                                 // aggregate: keep walking
            }
            // publish our inclusive prefix
            atomicExch(&g_state[blk],
                       (2ull << 32) | (unsigned long long)(unsigned)(exc + agg));
            s_exc = exc;
        }
    }
    __syncthreads();
    int exc = s_exc;

    if (i < NN) {
        int o = exc + incl - c;
        g_off[i] = o;
        g_pos[i] = o;
        g_inv[i] = 1.0f / fmaxf((float)c, 1.0f);
    }
}

// ---------------- CSR fill ----------------
__global__ void fill_kernel(const int* __restrict__ src,
                            const int* __restrict__ tgt) {
    int e = blockIdx.x * blockDim.x + threadIdx.x;
    if (e < EE) {
        int p = atomicAdd(&g_pos[tgt[e]], 1);
        g_adj[p] = src[e];
    }
}

// ---------------- gather: agg[n] = mean over in-neighbors of h[src] ----------------
template <int WHICH>
__global__ void gather_kernel() {
    const float* __restrict__ h = (WHICH == 0) ? g_h0 : g_h1;
    int idx = blockIdx.x * blockDim.x + threadIdx.x;
    int node = idx >> 5;
    if (node >= NN) return;
    int lane = idx & 31;

    int beg = g_off[node];
    int cnt = g_cnt[node];
    float4 acc = make_float4(0.f, 0.f, 0.f, 0.f);

    int i = 0;
    for (; i + 8 <= cnt; i += 8) {
        int sidx[8];
#pragma unroll
        for (int u = 0; u < 8; u++) sidx[u] = __ldg(&g_adj[beg + i + u]);
        float4 vv[8];
#pragma unroll
        for (int u = 0; u < 8; u++)
            vv[u] = *reinterpret_cast<const float4*>(h + sidx[u] * HH + lane * 4);
#pragma unroll
        for (int u = 0; u < 8; u++) {
            acc.x += vv[u].x; acc.y += vv[u].y;
            acc.z += vv[u].z; acc.w += vv[u].w;
        }
    }
    for (; i + 4 <= cnt; i += 4) {
        int s0 = __ldg(&g_adj[beg + i + 0]);
        int s1 = __ldg(&g_adj[beg + i + 1]);
        int s2 = __ldg(&g_adj[beg + i + 2]);
        int s3 = __ldg(&g_adj[beg + i + 3]);
        float4 v0 = *reinterpret_cast<const float4*>(h + s0 * HH + lane * 4);
        float4 v1 = *reinterpret_cast<const float4*>(h + s1 * HH + lane * 4);
        float4 v2 = *reinterpret_cast<const float4*>(h + s2 * HH + lane * 4);
        float4 v3 = *reinterpret_cast<const float4*>(h + s3 * HH + lane * 4);
        acc.x += v0.x + v1.x + v2.x + v3.x;
        acc.y += v0.y + v1.y + v2.y + v3.y;
        acc.z += v0.z + v1.z + v2.z + v3.z;
        acc.w += v0.w + v1.w + v2.w + v3.w;
    }
    for (; i < cnt; i++) {
        int s = __ldg(&g_adj[beg + i]);
        float4 v = *reinterpret_cast<const float4*>(h + s * HH + lane * 4);
        acc.x += v.x; acc.y += v.y; acc.z += v.z; acc.w += v.w;
    }
    float iv = g_inv[node];
    acc.x *= iv; acc.y *= iv; acc.z *= iv; acc.w *= iv;
    *reinterpret_cast<float4*>(g_agg + node * HH + lane * 4) = acc;
}

// ================= fused GCN layer via mma.sync tf32 =================
// 512 threads = 16 warps: warp grid 8 (m) x 2 (n); warp tile 16 x 64.
// CTA tile: 128 nodes x 128 cols; K = 128 per matrix, 2 matrices (h@ws + agg@wn).
#define SM_B2_F   0
#define SM_A_F    32768
#define SM_RS_F   49664
#define SM_RQ_F   49920
#define SM_G_F    50176
#define SM_BE_F   50304
#define SM_BI_F   50432
#define GCN_SMEM  (50560 * 4)
#define APITCH    132

template <int LAYER>
__global__ void __launch_bounds__(512, 1)
gcn_kernel(const float* __restrict__ ws, const float* __restrict__ bs,
           const float* __restrict__ wn, const float* __restrict__ bn,
           const float* __restrict__ gamma, const float* __restrict__ beta,
           float* __restrict__ out_param) {
    extern __shared__ float sm[];
    float2* B2   = reinterpret_cast<float2*>(sm + SM_B2_F);
    float*  sA   = sm + SM_A_F;
    float*  sredS = sm + SM_RS_F;
    float*  sredQ = sm + SM_RQ_F;
    float*  sg   = sm + SM_G_F;
    float*  sbe  = sm + SM_BE_F;
    float*  sbias = sm + SM_BI_F;

    const float* __restrict__ h_in = (LAYER == 0) ? g_h0 : g_h1;
    float* __restrict__ out = (LAYER == 0) ? g_h1 : out_param;

    int tid = threadIdx.x;
    int lane = tid & 31, wid = tid >> 5;
    int mr = wid >> 1;
    int wc = wid & 1;
    int ql = lane & 3, qr = lane >> 2;

    // ---- one-time: permute weights into B-fragment layout ----
    for (int e = tid; e < 16384; e += 512) {
        int l  = e & 31;
        int nf = (e >> 5) & 15;
        int s  = (e >> 9) & 15;
        int mat = e >> 13;
        const float* __restrict__ w = mat ? wn : ws;
        int k = s * 8 + (l & 3);
        int n = nf * 8 + (l >> 2);
        float2 b;
        b.x = __uint_as_float(f2tf32(w[k * HH + n]));
        b.y = __uint_as_float(f2tf32(w[(k + 4) * HH + n]));
        B2[e] = b;
    }
    for (int i = tid; i < HH; i += 512) {
        sg[i] = gamma[i];
        sbe[i] = beta[i];
        sbias[i] = bs[i] + bn[i];
    }
    __syncthreads();

    for (int tile = blockIdx.x; tile < NTILES; tile += gridDim.x) {
        int base = tile * 128;

        float acc[8][4];
#pragma unroll
        for (int nf = 0; nf < 8; nf++)
#pragma unroll
            for (int i = 0; i < 4; i++) acc[nf][i] = 0.f;

#pragma unroll
        for (int mat = 0; mat < 2; mat++) {
            const float* __restrict__ src = mat ? g_agg : h_in;
#pragma unroll
            for (int q = 0; q < 8; q++) {
                int id = q * 512 + tid;
                int r = id >> 5, c4 = (id & 31) * 4;
                int node = base + r;
                float4 v = make_float4(0.f, 0.f, 0.f, 0.f);
                if (node < NN)
                    v = *reinterpret_cast<const float4*>(src + node * HH + c4);
                float4 t;
                t.x = __uint_as_float(f2tf32(v.x));
                t.y = __uint_as_float(f2tf32(v.y));
                t.z = __uint_as_float(f2tf32(v.z));
                t.w = __uint_as_float(f2tf32(v.w));
                *reinterpret_cast<float4*>(sA + r * APITCH + c4) = t;
            }
            __syncthreads();

            int r0 = mr * 16 + qr;
            for (int s = 0; s < 16; s++) {
                int k = s * 8 + ql;
                uint32_t a0 = __float_as_uint(sA[r0 * APITCH + k]);
                uint32_t a1 = __float_as_uint(sA[(r0 + 8) * APITCH + k]);
                uint32_t a2 = __float_as_uint(sA[r0 * APITCH + k + 4]);
                uint32_t a3 = __float_as_uint(sA[(r0 + 8) * APITCH + k + 4]);
                const float2* bp = B2 + ((mat * 16 + s) * 16 + wc * 8) * 32 + lane;
#pragma unroll
                for (int nf = 0; nf < 8; nf++) {
                    float2 b = bp[nf * 32];
                    mma_tf32(acc[nf], a0, a1, a2, a3,
                             __float_as_uint(b.x), __float_as_uint(b.y));
                }
            }
            __syncthreads();
        }

        // ---- epilogue: +bias, LN stats, normalize, [relu+residual], store ----
        int row_lo = mr * 16 + qr;
        int row_hi = row_lo + 8;
        float s_lo = 0.f, q_lo = 0.f, s_hi = 0.f, q_hi = 0.f;
#pragma unroll
        for (int nf = 0; nf < 8; nf++) {
            int c0 = wc * 64 + nf * 8 + 2 * ql;
            acc[nf][0] += sbias[c0];
            acc[nf][1] += sbias[c0 + 1];
            acc[nf][2] += sbias[c0];
            acc[nf][3] += sbias[c0 + 1];
            s_lo += acc[nf][0] + acc[nf][1];
            q_lo += acc[nf][0] * acc[nf][0] + acc[nf][1] * acc[nf][1];
            s_hi += acc[nf][2] + acc[nf][3];
            q_hi += acc[nf][2] * acc[nf][2] + acc[nf][3] * acc[nf][3];
        }
#pragma unroll
        for (int o = 1; o <= 2; o <<= 1) {
            s_lo += __shfl_xor_sync(0xffffffffu, s_lo, o);
            q_lo += __shfl_xor_sync(0xffffffffu, q_lo, o);
            s_hi += __shfl_xor_sync(0xffffffffu, s_hi, o);
            q_hi += __shfl_xor_sync(0xffffffffu, q_hi, o);
        }
        if (ql == 0) {
            sredS[row_lo * 2 + wc] = s_lo;
            sredQ[row_lo * 2 + wc] = q_lo;
            sredS[row_hi * 2 + wc] = s_hi;
            sredQ[row_hi * 2 + wc] = q_hi;
        }
        __syncthreads();
        float S_lo = sredS[row_lo * 2] + sredS[row_lo * 2 + 1];
        float Q_lo = sredQ[row_lo * 2] + sredQ[row_lo * 2 + 1];
        float S_hi = sredS[row_hi * 2] + sredS[row_hi * 2 + 1];
        float Q_hi = sredQ[row_hi * 2] + sredQ[row_hi * 2 + 1];
        float mean_lo = S_lo * (1.0f / HH);
        float var_lo = Q_lo * (1.0f / HH) - mean_lo * mean_lo;
        float rstd_lo = rsqrtf(var_lo + LN_EPS);
        float mean_hi = S_hi * (1.0f / HH);
        float var_hi = Q_hi * (1.0f / HH) - mean_hi * mean_hi;
        float rstd_hi = rsqrtf(var_hi + LN_EPS);

        int node_lo = base + row_lo;
        int node_hi = base + row_hi;
#pragma unroll
        for (int nf = 0; nf < 8; nf++) {
            int c0 = wc * 64 + nf * 8 + 2 * ql;
            float g0v = sg[c0], g1v = sg[c0 + 1];
            float b0v = sbe[c0], b1v = sbe[c0 + 1];
            if (node_lo < NN) {
                float2 y;
                y.x = (acc[nf][0] - mean_lo) * rstd_lo * g0v + b0v;
                y.y = (acc[nf][1] - mean_lo) * rstd_lo * g1v + b1v;
                if (LAYER == 0) {
                    float2 res = *reinterpret_cast<const float2*>(
                        h_in + node_lo * HH + c0);
                    y.x = fmaxf(y.x, 0.f) + res.x;
                    y.y = fmaxf(y.y, 0.f) + res.y;
                }
                *reinterpret_cast<float2*>(out + node_lo * HH + c0) = y;
            }
            if (node_hi < NN) {
                float2 y;
                y.x = (acc[nf][2] - mean_hi) * rstd_hi * g0v + b0v;
                y.y = (acc[nf][3] - mean_hi) * rstd_hi * g1v + b1v;
                if (LAYER == 0) {
                    float2 res = *reinterpret_cast<const float2*>(
                        h_in + node_hi * HH + c0);
                    y.x = fmaxf(y.x, 0.f) + res.x;
                    y.y = fmaxf(y.y, 0.f) + res.y;
                }
                *reinterpret_cast<float2*>(out + node_hi * HH + c0) = y;
            }
        }
        __syncthreads();
    }
}

// ---------------- launch ----------------
extern "C" void kernel_launch(void* const* d_in, const int* in_sizes, int n_in,
                              void* d_out, int out_size) {
    const float* x    = (const float*)d_in[0];
    const int*   ei   = (const int*)d_in[1];
    const float* w_in = (const float*)d_in[2];
    const float* b_in = (const float*)d_in[3];
    const float* ws0  = (const float*)d_in[4];
    const float* bs0  = (const float*)d_in[5];
    const float* wn0  = (const float*)d_in[6];
    const float* bn0  = (const float*)d_in[7];
    const float* g0   = (const float*)d_in[8];
    const float* be0  = (const float*)d_in[9];
    const float* ws1  = (const float*)d_in[10];
    const float* bs1  = (const float*)d_in[11];
    const float* wn1  = (const float*)d_in[12];
    const float* bn1  = (const float*)d_in[13];
    const float* g1   = (const float*)d_in[14];
    const float* be1  = (const float*)d_in[15];
    float* out = (float*)d_out;

    const int* src = ei;
    const int* tgt = ei + EE;

    cudaFuncSetAttribute(gcn_kernel<0>, cudaFuncAttributeMaxDynamicSharedMemorySize, GCN_SMEM);
    cudaFuncSetAttribute(gcn_kernel<1>, cudaFuncAttributeMaxDynamicSharedMemorySize, GCN_SMEM);

    input_proj_kernel<<<512, 256>>>(x, w_in, b_in);      // also zeros cnt/state
    count_kernel<<<(EE + 255) / 256, 256>>>(tgt);
    scan_kernel<<<NB, 256>>>();                           // single-pass lookback
    fill_kernel<<<(EE + 255) / 256, 256>>>(src, tgt);
    gather_kernel<0><<<(NN * 32 + 255) / 256, 256>>>();
    gcn_kernel<0><<<148, 512, GCN_SMEM>>>(ws0, bs0, wn0, bn0, g0, be0, nullptr);
    gather_kernel<1><<<(NN * 32 + 255) / 256, 256>>>();
    gcn_kernel<1><<<148, 512, GCN_SMEM>>>(ws1, bs1, wn1, bn1, g1, be1, out);
}